// round 16
// baseline (speedup 1.0000x reference)
#include <cuda_runtime.h>
#include <cstdint>

#define NB 888              // 6 CTAs/SM x 148 SMs
#define NT 256
#define CHUNK 256           // samples per chunk
#define CHUNK_BYTES (CHUNK * 32)   // 8 KB per array per stage

// Zero-initialized at module load; finalizing block resets after each run.
__device__ double       g_ce;
__device__ unsigned int g_row[8];
__device__ unsigned int g_col[8];
__device__ unsigned int g_diag[8];
__device__ unsigned int g_done;

__device__ __forceinline__ unsigned sm_u32(const void* p) {
    return (unsigned)__cvta_generic_to_shared(p);
}

__device__ __forceinline__ void mbar_wait(unsigned mb, unsigned phase) {
    unsigned done;
    asm volatile(
        "{ .reg .pred p; mbarrier.try_wait.parity.acquire.cta.shared::cta.b64 p, [%1], %2;"
        " selp.b32 %0, 1, 0, p; }"
        : "=r"(done) : "r"(mb), "r"(phase) : "memory");
    if (!done) {
        asm volatile(
            "{ .reg .pred P1;\n"
            "WL_%=: mbarrier.try_wait.parity.acquire.cta.shared::cta.b64 P1, [%0], %1, 0x989680;\n"
            "@P1 bra.uni WD_%=;\n"
            "bra.uni WL_%=;\n"
            "WD_%=: }"
            :: "r"(mb), "r"(phase) : "memory");
    }
}

struct Acc { float ce; unsigned rlo, rhi, clo, chi, dlo, dhi; };

// R12's per-sample body, unchanged.
__device__ __forceinline__ void process_sample(
    float4 a0, float4 a1, float4 b0, float4 b1, const float* cw_s, Acc& ac)
{
    float x[8]  = {a0.x, a0.y, a0.z, a0.w, a1.x, a1.y, a1.z, a1.w};
    float gv[8] = {b0.x, b0.y, b0.z, b0.w, b1.x, b1.y, b1.z, b1.w};

    float fg = gv[1];
    fg = fmaf(2.0f, gv[2], fg); fg = fmaf(3.0f, gv[3], fg);
    fg = fmaf(4.0f, gv[4], fg); fg = fmaf(5.0f, gv[5], fg);
    fg = fmaf(6.0f, gv[6], fg); fg = fmaf(7.0f, gv[7], fg);
    int gi = __float2int_rn(fg);
    float wg = cw_s[gi];

    float e[8]; float S = 0.0f, eg = 0.0f;
    #pragma unroll
    for (int j = 0; j < 8; j++) {
        e[j] = __expf(x[j]);           // x ~ N(0,1): EX2 range-safe
        S  += e[j];
        eg  = fmaf(e[j], gv[j], eg);
    }

    unsigned kmax = (__float_as_uint(e[0]) & ~7u) | 7u;
    #pragma unroll
    for (int j = 1; j < 8; j++) {
        unsigned key = (__float_as_uint(e[j]) & ~7u) | (unsigned)(7 - j);
        kmax = max(kmax, key);
    }
    int pa = 7 - (int)(kmax & 7u);

    float r  = __fdividef(1.0f, S);
    float pg = eg * r;
    float r2 = r * 1.4426950408889634f;

    float S2 = 0.0f;
    #pragma unroll
    for (int j = 0; j < 8; j++) S2 += exp2f(e[j] * r2);

    float lse2 = __logf(S2);
    ac.ce = fmaf(wg, lse2 - pg, ac.ce);

    unsigned rinc = 1u << ((gi & 3) << 3);
    if (gi < 4) ac.rlo += rinc; else ac.rhi += rinc;
    unsigned cinc = 1u << ((pa & 3) << 3);
    if (pa < 4) ac.clo += cinc; else ac.chi += cinc;
    if (gi == pa) { if (gi < 4) ac.dlo += rinc; else ac.dhi += rinc; }
}

__global__ void __launch_bounds__(NT, 6)
fused_k(const char* __restrict__ predB, const char* __restrict__ gtB,
        const float* __restrict__ cw, float* __restrict__ out,
        int B, double invB)
{
    __shared__ __align__(16) char bufP[2][CHUNK_BYTES];
    __shared__ __align__(16) char bufG[2][CHUNK_BYTES];
    __shared__ uint64_t mbar[2];
    __shared__ unsigned int row_s[8], col_s[8], diag_s[8];
    __shared__ float cw_s[8];
    __shared__ float warpsum[NT / 32];
    __shared__ unsigned int s_ticket;

    int t = threadIdx.x;
    if (t < 8) { row_s[t] = 0u; col_s[t] = 0u; diag_s[t] = 0u; cw_s[t] = __ldg(&cw[t]); }
    if (t == 0) {
        asm volatile("mbarrier.init.shared.b64 [%0], %1;" :: "r"(sm_u32(&mbar[0])), "r"(1) : "memory");
        asm volatile("mbarrier.init.shared.b64 [%0], %1;" :: "r"(sm_u32(&mbar[1])), "r"(1) : "memory");
    }
    __syncthreads();

    int nch = B / CHUNK;   // bench shape: B = 4194304 = 16384 * 256 (rem handled below)

    Acc ac = {0.0f, 0u, 0u, 0u, 0u, 0u, 0u};
    int c = blockIdx.x;
    unsigned ph[2] = {0u, 0u};
    int s = 0;

    // prologue: load chunk c into stage 0 via bulk-async (TMA engine path)
    if (c < nch && t == 0) {
        unsigned mb = sm_u32(&mbar[0]);
        asm volatile("mbarrier.arrive.expect_tx.shared.b64 _, [%0], %1;"
                     :: "r"(mb), "r"(2 * CHUNK_BYTES) : "memory");
        long off = (long)c * CHUNK_BYTES;
        asm volatile("cp.async.bulk.shared::cluster.global.mbarrier::complete_tx::bytes [%0], [%1], %2, [%3];"
                     :: "r"(sm_u32(&bufP[0][0])), "l"(predB + off), "r"(CHUNK_BYTES), "r"(mb) : "memory");
        asm volatile("cp.async.bulk.shared::cluster.global.mbarrier::complete_tx::bytes [%0], [%1], %2, [%3];"
                     :: "r"(sm_u32(&bufG[0][0])), "l"(gtB + off), "r"(CHUNK_BYTES), "r"(mb) : "memory");
    }

    while (c < nch) {
        // issue NEXT chunk into the other stage (freed by last iter's barrier)
        int cn = c + NB;
        if (cn < nch && t == 0) {
            int d = s ^ 1;
            unsigned mb = sm_u32(&mbar[d]);
            asm volatile("mbarrier.arrive.expect_tx.shared.b64 _, [%0], %1;"
                         :: "r"(mb), "r"(2 * CHUNK_BYTES) : "memory");
            long off = (long)cn * CHUNK_BYTES;
            asm volatile("cp.async.bulk.shared::cluster.global.mbarrier::complete_tx::bytes [%0], [%1], %2, [%3];"
                         :: "r"(sm_u32(&bufP[d][0])), "l"(predB + off), "r"(CHUNK_BYTES), "r"(mb) : "memory");
            asm volatile("cp.async.bulk.shared::cluster.global.mbarrier::complete_tx::bytes [%0], [%1], %2, [%3];"
                         :: "r"(sm_u32(&bufG[d][0])), "l"(gtB + off), "r"(CHUNK_BYTES), "r"(mb) : "memory");
        }

        mbar_wait(sm_u32(&mbar[s]), ph[s]);
        ph[s] ^= 1u;

        const float4* sp = (const float4*)(bufP[s] + t * 32);
        const float4* sg = (const float4*)(bufG[s] + t * 32);
        float4 a0 = sp[0], a1 = sp[1];
        float4 b0 = sg[0], b1 = sg[1];
        process_sample(a0, a1, b0, b1, cw_s, ac);

        __syncthreads();   // stage s readable done -> reusable at next issue
        c = cn; s ^= 1;
    }

    // tail (rem != 0 only if B not divisible by CHUNK): CTA 0 handles via LDG
    int rem = B - nch * CHUNK;
    if (rem > 0 && blockIdx.x == 0) {
        for (int i = nch * CHUNK + t; i < B; i += NT) {
            const float4* pp = (const float4*)(predB + (long)i * 32);
            const float4* gp = (const float4*)(gtB   + (long)i * 32);
            process_sample(__ldg(pp), __ldg(pp + 1), __ldg(gp), __ldg(gp + 1), cw_s, ac);
        }
    }

    // ---- CE reduction
    float ce = ac.ce;
    #pragma unroll
    for (int o = 16; o > 0; o >>= 1) ce += __shfl_down_sync(0xFFFFFFFFu, ce, o);
    if ((t & 31) == 0) warpsum[t >> 5] = ce;

    // ---- histogram flush: 8b->16b split, REDUX, lane0 atomics
    {
        int lane = t & 31;
        unsigned pk[6] = {ac.rlo, ac.rhi, ac.clo, ac.chi, ac.dlo, ac.dhi};
        unsigned int* dsts[3] = {row_s, col_s, diag_s};
        #pragma unroll
        for (int h = 0; h < 3; h++) {
            unsigned lo = pk[2 * h], hi = pk[2 * h + 1];
            unsigned a = __reduce_add_sync(0xFFFFFFFFu, lo & 0x00FF00FFu);
            unsigned b = __reduce_add_sync(0xFFFFFFFFu, (lo >> 8) & 0x00FF00FFu);
            unsigned cc = __reduce_add_sync(0xFFFFFFFFu, hi & 0x00FF00FFu);
            unsigned d = __reduce_add_sync(0xFFFFFFFFu, (hi >> 8) & 0x00FF00FFu);
            if (lane == 0) {
                atomicAdd(&dsts[h][0], a & 0xFFFFu);  atomicAdd(&dsts[h][2], a >> 16);
                atomicAdd(&dsts[h][1], b & 0xFFFFu);  atomicAdd(&dsts[h][3], b >> 16);
                atomicAdd(&dsts[h][4], cc & 0xFFFFu); atomicAdd(&dsts[h][6], cc >> 16);
                atomicAdd(&dsts[h][5], d & 0xFFFFu);  atomicAdd(&dsts[h][7], d >> 16);
            }
        }
    }
    __syncthreads();

    if (t == 0) {
        double sm = 0.0;
        #pragma unroll
        for (int k = 0; k < NT / 32; k++) sm += (double)warpsum[k];
        atomicAdd(&g_ce, sm);
    }
    if (t < 8) {
        atomicAdd(&g_row[t],  row_s[t]);
        atomicAdd(&g_col[t],  col_s[t]);
        atomicAdd(&g_diag[t], diag_s[t]);
    }

    // ---- last-block-done finalize
    __syncthreads();
    if (t == 0) {
        __threadfence();
        s_ticket = atomicAdd(&g_done, 1u);
    }
    __syncthreads();

    if (s_ticket == (unsigned)(gridDim.x - 1) && t == 0) {
        float dice_loss = 0.0f;
        #pragma unroll 1
        for (int ii = 0; ii < 8; ii++) {
            float row = (float)(*((volatile unsigned int*)&g_row[ii]));
            float col = (float)(*((volatile unsigned int*)&g_col[ii]));
            float tp  = (float)(*((volatile unsigned int*)&g_diag[ii]));
            float dice = (tp + 1e-8f) / (row + col - tp + 1e-8f);
            dice_loss += (1.0f - dice) * cw_s[ii];
        }
        dice_loss *= 0.125f;
        double ce_tot = *((volatile double*)&g_ce);
        out[0] = (float)(ce_tot * invB + 0.5 * (double)dice_loss);

        g_ce = 0.0;
        #pragma unroll 1
        for (int k = 0; k < 8; k++) { g_row[k] = 0u; g_col[k] = 0u; g_diag[k] = 0u; }
        __threadfence();
        g_done = 0u;
    }
}

extern "C" void kernel_launch(void* const* d_in, const int* in_sizes, int n_in,
                              void* d_out, int out_size) {
    const char*  pred = (const char*)d_in[0];
    const char*  gt   = (const char*)d_in[1];
    const float* cw   = (const float*)d_in[2];
    float* out = (float*)d_out;
    int B = in_sizes[0] / 8;

    fused_k<<<NB, NT>>>(pred, gt, cw, out, B, 1.0 / (double)B);
}